// round 9
// baseline (speedup 1.0000x reference)
#include <cuda_runtime.h>
#include <math.h>

#define NNODES 30000
#define FIN    500
#define HID    16
#define OUTC   3
#define NEDGE  960000

typedef unsigned long long ull;

// ---------------- scratch (static device arrays; no allocation) -------------
__device__ float g_h0  [NNODES * HID];
__device__ float g_lin1[NNODES * HID];
__device__ float g_acc1[NNODES * HID];
__device__ float g_lin2[NNODES * 4];
__device__ float g_acc2[NNODES * 4];
__device__ int   g_deg [NNODES];
__device__ float g_dinv[NNODES];

// ---------------- f32x2 packed-FMA helpers (sm_103a FFMA2) ------------------
__device__ __forceinline__ ull fma2(ull a, ull b, ull c)
{
    ull d;
    asm("fma.rn.f32x2 %0, %1, %2, %3;" : "=l"(d) : "l"(a), "l"(b), "l"(c));
    return d;
}
__device__ __forceinline__ ull dup2(float x)
{
    ull d;
    asm("mov.b64 %0, {%1, %1};" : "=l"(d) : "f"(x));
    return d;
}
__device__ __forceinline__ float2 unpk(ull v)
{
    float2 r;
    asm("mov.b64 {%0, %1}, %2;" : "=f"(r.x), "=f"(r.y) : "l"(v));
    return r;
}

// ---------------- 128-bit global float4 reduction (sm_90+) -------------------
__device__ __forceinline__ void red_add_v4(float* p, float a, float b, float c, float d)
{
    asm volatile("red.global.add.v4.f32 [%0], {%1, %2, %3, %4};"
                 :: "l"(p), "f"(a), "f"(b), "f"(c), "f"(d) : "memory");
}

// ---------------- dynamic-smem layout for the conv kernel --------------------
// s[ch][k] holds conv1 activation a[k-2] DUPLICATED into both 32-bit halves.
// k in [0,504): borders k=0,1 (a[-2],a[-1]) and k=502,503 (a[500],a[501]) = 0.
struct ConvSmem {
    ull   s[HID][504];                   // 64512 B, 16B-aligned rows (stride 4032)
    float xs[512];
    float ws2p[HID * 3 * 16];            // [ic][tap][oc] transposed conv2 weights
    float ws1p[8 * 3 * 2];               // conv1 weights packed over channel pairs
    float bs1[16];
    float bs2[16];                       // 16B-aligned (offset multiple of 16)
    float red[4][16];
};
#define CONV_SMEM_BYTES (sizeof(ConvSmem))

// ---------------- fused conv1 -> relu -> conv2 -> relu -> max ----------------
// one block per node, 512 threads.
// Phase 2: tid = g*128 + q. Thread covers oc 4g..4g+3, positions {2q,2q+1} and
// {256+2q, 257+2q} (second sweep valid for q<=121). Zero dup-MOVs in the loop.
__global__ __launch_bounds__(512, 2)
void conv_max_kernel(const float* __restrict__ x,
                     const float* __restrict__ w1, const float* __restrict__ b1,
                     const float* __restrict__ w2, const float* __restrict__ b2)
{
    extern __shared__ __align__(16) char smem_raw[];
    ConvSmem* sm = reinterpret_cast<ConvSmem*>(smem_raw);

    const int tid = threadIdx.x;
    const int n   = blockIdx.x;

    // --- phase 0: load x, stage weights, zero borders ------------------------
    {
        if (tid == 0) g_deg[n] = 0;

        if (tid < 502)
            sm->xs[tid] = (tid == 0 || tid == 501) ? 0.f : x[n * FIN + (tid - 1)];

        // border dup-cells: k = 0,1,502,503 for each channel
        if (tid < 64) {
            const int ch = tid >> 2;
            const int kk = tid & 3;
            const int k  = (kk < 2) ? kk : (500 + kk);
            sm->s[ch][k] = 0ull;
        }

        // ws2p[(ic*3 + t)*16 + oc] = w2[oc*48 + ic*3 + t]
        for (int i = tid; i < HID * 3 * HID; i += 512) {
            int ic  = i / 48;
            int rem = i - ic * 48;
            int t   = rem >> 4;
            int oc  = rem & 15;
            sm->ws2p[i] = w2[oc * 48 + ic * 3 + t];
        }
        if (tid < 48) {
            int c = tid / 3, t = tid - c * 3;
            sm->ws1p[((c >> 1) * 3 + t) * 2 + (c & 1)] = w1[tid];
        } else if (tid < 64)  sm->bs1[tid - 48] = b1[tid - 48];
        else if (tid < 80)    sm->bs2[tid - 64] = b2[tid - 64];
    }
    __syncthreads();

    // --- phase 1: conv1 (FFMA2) + relu, stored DUPLICATED --------------------
    if (tid < FIN) {
        const ull dm = dup2(sm->xs[tid]);
        const ull d0 = dup2(sm->xs[tid + 1]);
        const ull dp = dup2(sm->xs[tid + 2]);
        #pragma unroll
        for (int cp = 0; cp < 8; cp++) {
            ull acc = *reinterpret_cast<const ull*>(&sm->ws1p[0]) , tmp; // placeholder type
            acc = *reinterpret_cast<const ull*>(&sm->bs1[2 * cp]);
            acc = fma2(*reinterpret_cast<const ull*>(&sm->ws1p[(cp * 3 + 0) * 2]), dm, acc);
            acc = fma2(*reinterpret_cast<const ull*>(&sm->ws1p[(cp * 3 + 1) * 2]), d0, acc);
            acc = fma2(*reinterpret_cast<const ull*>(&sm->ws1p[(cp * 3 + 2) * 2]), dp, acc);
            const float2 u = unpk(acc);
            sm->s[2 * cp + 0][tid + 2] = dup2(fmaxf(u.x, 0.f));
            sm->s[2 * cp + 1][tid + 2] = dup2(fmaxf(u.y, 0.f));
            (void)tmp;
        }
    }
    __syncthreads();

    // --- phase 2: conv2 via FFMA2 with pre-duplicated activations ------------
    {
        const int g  = tid >> 7;        // oc group: 4g..4g+3
        const int q  = tid & 127;
        const int p0a = 2 * q;                    // sweep 0: positions p0a, p0a+1
        const bool v1 = (q <= 121);
        const int p0b = v1 ? (256 + 2 * q) : 256; // sweep 1 (clamped if invalid)

        const ull b01 = *reinterpret_cast<const ull*>(&sm->bs2[4 * g]);
        const ull b23 = *reinterpret_cast<const ull*>(&sm->bs2[4 * g + 2]);

        // acc[it][pos][pair]
        ull acc[2][2][2];
        #pragma unroll
        for (int it = 0; it < 2; it++)
            #pragma unroll
            for (int ps = 0; ps < 2; ps++) { acc[it][ps][0] = b01; acc[it][ps][1] = b23; }

        #pragma unroll
        for (int ic = 0; ic < HID; ic++) {
            const ulonglong2 w0 = *reinterpret_cast<const ulonglong2*>(&sm->ws2p[(ic * 3 + 0) * 16 + 4 * g]);
            const ulonglong2 w1v = *reinterpret_cast<const ulonglong2*>(&sm->ws2p[(ic * 3 + 1) * 16 + 4 * g]);
            const ulonglong2 w2v = *reinterpret_cast<const ulonglong2*>(&sm->ws2p[(ic * 3 + 2) * 16 + 4 * g]);

            #pragma unroll
            for (int it = 0; it < 2; it++) {
                const int p0 = it ? p0b : p0a;
                // s index k = position + 2 ; loads 16B-aligned (p0 even)
                const ulonglong2 A = *reinterpret_cast<const ulonglong2*>(&sm->s[ic][p0]);     // dup a[p0-2], a[p0-1]
                const ulonglong2 B = *reinterpret_cast<const ulonglong2*>(&sm->s[ic][p0 + 2]); // dup a[p0],   a[p0+1]
                const ulonglong2 C = *reinterpret_cast<const ulonglong2*>(&sm->s[ic][p0 + 4]); // dup a[p0+2], a[p0+3]
                const ull dm = A.y, d0 = B.x, d1 = B.y, d2 = C.x;

                // y[p0]  : taps (dm, d0, d1)
                acc[it][0][0] = fma2(w0.x,  dm, acc[it][0][0]);
                acc[it][0][1] = fma2(w0.y,  dm, acc[it][0][1]);
                acc[it][0][0] = fma2(w1v.x, d0, acc[it][0][0]);
                acc[it][0][1] = fma2(w1v.y, d0, acc[it][0][1]);
                acc[it][0][0] = fma2(w2v.x, d1, acc[it][0][0]);
                acc[it][0][1] = fma2(w2v.y, d1, acc[it][0][1]);
                // y[p0+1]: taps (d0, d1, d2)
                acc[it][1][0] = fma2(w0.x,  d0, acc[it][1][0]);
                acc[it][1][1] = fma2(w0.y,  d0, acc[it][1][1]);
                acc[it][1][0] = fma2(w1v.x, d1, acc[it][1][0]);
                acc[it][1][1] = fma2(w1v.y, d1, acc[it][1][1]);
                acc[it][1][0] = fma2(w2v.x, d2, acc[it][1][0]);
                acc[it][1][1] = fma2(w2v.y, d2, acc[it][1][1]);
            }
        }

        float mx0 = -1e30f, mx1 = -1e30f, mx2 = -1e30f, mx3 = -1e30f;
        #pragma unroll
        for (int it = 0; it < 2; it++) {
            if (it == 1 && !v1) break;
            #pragma unroll
            for (int ps = 0; ps < 2; ps++) {
                const float2 u0 = unpk(acc[it][ps][0]);
                const float2 u1 = unpk(acc[it][ps][1]);
                mx0 = fmaxf(mx0, u0.x); mx1 = fmaxf(mx1, u0.y);
                mx2 = fmaxf(mx2, u1.x); mx3 = fmaxf(mx3, u1.y);
            }
        }
        #pragma unroll
        for (int off = 16; off; off >>= 1) {
            mx0 = fmaxf(mx0, __shfl_xor_sync(0xffffffffu, mx0, off));
            mx1 = fmaxf(mx1, __shfl_xor_sync(0xffffffffu, mx1, off));
            mx2 = fmaxf(mx2, __shfl_xor_sync(0xffffffffu, mx2, off));
            mx3 = fmaxf(mx3, __shfl_xor_sync(0xffffffffu, mx3, off));
        }
        const int lane = tid & 31;
        const int wig  = (tid >> 5) & 3;
        if (lane == 0) {
            sm->red[wig][4 * g + 0] = mx0;
            sm->red[wig][4 * g + 1] = mx1;
            sm->red[wig][4 * g + 2] = mx2;
            sm->red[wig][4 * g + 3] = mx3;
        }
        __syncthreads();
        if (tid < HID) {
            float m = fmaxf(fmaxf(sm->red[0][tid], sm->red[1][tid]),
                            fmaxf(sm->red[2][tid], sm->red[3][tid]));
            g_h0[n * HID + tid] = fmaxf(m, 0.f);
        }
    }
}

// ---------------- degree count (g_deg zeroed in conv_max) --------------------
__global__ void deg_count_kernel(const int* __restrict__ dst)
{
    int i = blockIdx.x * blockDim.x + threadIdx.x;
    if (i < NEDGE) atomicAdd(&g_deg[dst[i]], 1);
}

// ---------------- gcn1: dinv + linear + self-loop init -----------------------
__global__ void lin1_kernel(const float* __restrict__ W, const float* __restrict__ b)
{
    __shared__ float Ws[HID * HID];
    __shared__ float bs[HID];
    const int tid = threadIdx.x;
    if (tid < HID * HID) Ws[tid] = W[tid];
    if (tid < HID)       bs[tid] = b[tid];
    __syncthreads();

    const int i = blockIdx.x * blockDim.x + tid;
    if (i >= NNODES) return;

    float h[HID];
    const float4* hp = reinterpret_cast<const float4*>(&g_h0[i * HID]);
    #pragma unroll
    for (int q = 0; q < 4; q++) {
        float4 v = hp[q];
        h[q * 4 + 0] = v.x; h[q * 4 + 1] = v.y; h[q * 4 + 2] = v.z; h[q * 4 + 3] = v.w;
    }
    float acc[HID];
    #pragma unroll
    for (int c = 0; c < HID; c++) acc[c] = 0.f;
    #pragma unroll
    for (int in = 0; in < HID; in++) {
        const float hv = h[in];
        #pragma unroll
        for (int c = 0; c < HID; c++) acc[c] = fmaf(hv, Ws[in * HID + c], acc[c]);
    }
    const float di = rsqrtf((float)(g_deg[i] + 1));
    g_dinv[i] = di;
    const float d2 = di * di;
    #pragma unroll
    for (int c = 0; c < HID; c++) {
        g_lin1[i * HID + c] = acc[c];
        g_acc1[i * HID + c] = fmaf(d2, acc[c], bs[c]);
    }
}

// ---------------- gcn1: edge scatter (1 thread/edge, 4x red.v4.f32) ----------
__global__ void scatter1_kernel(const int* __restrict__ src, const int* __restrict__ dst)
{
    int e = blockIdx.x * blockDim.x + threadIdx.x;
    if (e >= NEDGE) return;
    const int s = src[e];
    const int d = dst[e];
    const float w = g_dinv[s] * g_dinv[d];
    const float4* vp = reinterpret_cast<const float4*>(&g_lin1[s * HID]);
    float* out = &g_acc1[d * HID];
    #pragma unroll
    for (int q = 0; q < 4; q++) {
        const float4 v = vp[q];
        red_add_v4(out + 4 * q, w * v.x, w * v.y, w * v.z, w * v.w);
    }
}

// ---------------- gcn2: relu + linear(16->3) + self-loop init ----------------
__global__ void lin2_kernel(const float* __restrict__ W, const float* __restrict__ b)
{
    __shared__ float Ws[HID * OUTC];
    __shared__ float bs[OUTC];
    const int tid = threadIdx.x;
    if (tid < HID * OUTC) Ws[tid] = W[tid];
    if (tid < OUTC)       bs[tid] = b[tid];
    __syncthreads();

    const int i = blockIdx.x * blockDim.x + tid;
    if (i >= NNODES) return;

    float h[HID];
    const float4* hp = reinterpret_cast<const float4*>(&g_acc1[i * HID]);
    #pragma unroll
    for (int q = 0; q < 4; q++) {
        float4 v = hp[q];
        h[q * 4 + 0] = fmaxf(v.x, 0.f); h[q * 4 + 1] = fmaxf(v.y, 0.f);
        h[q * 4 + 2] = fmaxf(v.z, 0.f); h[q * 4 + 3] = fmaxf(v.w, 0.f);
    }
    float acc[OUTC] = {0.f, 0.f, 0.f};
    #pragma unroll
    for (int in = 0; in < HID; in++) {
        const float hv = h[in];
        #pragma unroll
        for (int c = 0; c < OUTC; c++) acc[c] = fmaf(hv, Ws[in * OUTC + c], acc[c]);
    }
    const float di = g_dinv[i];
    const float d2 = di * di;
    #pragma unroll
    for (int c = 0; c < OUTC; c++) {
        g_lin2[i * 4 + c] = acc[c];
        g_acc2[i * 4 + c] = fmaf(d2, acc[c], bs[c]);
    }
    g_lin2[i * 4 + 3] = 0.f;
    g_acc2[i * 4 + 3] = 0.f;
}

// ---------------- gcn2: edge scatter (1 thread/edge, 1x red.v4.f32) ----------
__global__ void scatter2_kernel(const int* __restrict__ src, const int* __restrict__ dst)
{
    int e = blockIdx.x * blockDim.x + threadIdx.x;
    if (e >= NEDGE) return;
    const int s = src[e];
    const int d = dst[e];
    const float w = g_dinv[s] * g_dinv[d];
    const float4 v = *reinterpret_cast<const float4*>(&g_lin2[s * 4]);
    red_add_v4(&g_acc2[d * 4], w * v.x, w * v.y, w * v.z, 0.f);
}

// ---------------- log_softmax ------------------------------------------------
__global__ void logsoftmax_kernel(float* __restrict__ out)
{
    int i = blockIdx.x * blockDim.x + threadIdx.x;
    if (i >= NNODES) return;
    const float z0 = g_acc2[i * 4 + 0];
    const float z1 = g_acc2[i * 4 + 1];
    const float z2 = g_acc2[i * 4 + 2];
    const float m  = fmaxf(z0, fmaxf(z1, z2));
    const float s  = expf(z0 - m) + expf(z1 - m) + expf(z2 - m);
    const float l  = m + logf(s);
    out[i * 3 + 0] = z0 - l;
    out[i * 3 + 1] = z1 - l;
    out[i * 3 + 2] = z2 - l;
}

// ---------------- launcher ---------------------------------------------------
extern "C" void kernel_launch(void* const* d_in, const int* in_sizes, int n_in,
                              void* d_out, int out_size)
{
    const float* x       = (const float*)d_in[0];
    const float* conv1_w = (const float*)d_in[1];
    const float* conv1_b = (const float*)d_in[2];
    const float* conv2_w = (const float*)d_in[3];
    const float* conv2_b = (const float*)d_in[4];
    const float* gcn1_w  = (const float*)d_in[5];
    const float* gcn1_b  = (const float*)d_in[6];
    const float* gcn2_w  = (const float*)d_in[7];
    const float* gcn2_b  = (const float*)d_in[8];
    const int*   edges   = (const int*)d_in[9];
    const int*   src     = edges;
    const int*   dst     = edges + NEDGE;
    float*       out     = (float*)d_out;

    cudaFuncSetAttribute(conv_max_kernel,
                         cudaFuncAttributeMaxDynamicSharedMemorySize,
                         (int)CONV_SMEM_BYTES);

    conv_max_kernel<<<NNODES, 512, CONV_SMEM_BYTES>>>(x, conv1_w, conv1_b, conv2_w, conv2_b);

    deg_count_kernel<<<(NEDGE + 255) / 256, 256>>>(dst);

    lin1_kernel    <<<(NNODES + 255) / 256, 256>>>(gcn1_w, gcn1_b);
    scatter1_kernel<<<(NEDGE + 255) / 256, 256>>>(src, dst);

    lin2_kernel    <<<(NNODES + 255) / 256, 256>>>(gcn2_w, gcn2_b);
    scatter2_kernel<<<(NEDGE + 255) / 256, 256>>>(src, dst);

    logsoftmax_kernel<<<(NNODES + 255) / 256, 256>>>(out);
}

// round 10
// speedup vs baseline: 1.6463x; 1.6463x over previous
#include <cuda_runtime.h>
#include <math.h>

#define NNODES 30000
#define FIN    500
#define HID    16
#define OUTC   3
#define NEDGE  960000

typedef unsigned long long ull;

// ---------------- scratch (static device arrays; no allocation) -------------
__device__ float g_h0  [NNODES * HID];
__device__ float g_lin1[NNODES * HID];
__device__ float g_acc1[NNODES * HID];
__device__ float g_lin2[NNODES * 4];
__device__ float g_acc2[NNODES * 4];
__device__ int   g_deg [NNODES];
__device__ float g_dinv[NNODES];

// ---------------- f32x2 packed-FMA helpers (sm_103a FFMA2) ------------------
__device__ __forceinline__ ull fma2(ull a, ull b, ull c)
{
    ull d;
    asm("fma.rn.f32x2 %0, %1, %2, %3;" : "=l"(d) : "l"(a), "l"(b), "l"(c));
    return d;
}
__device__ __forceinline__ ull dup2(float x)
{
    ull d;
    asm("mov.b64 %0, {%1, %1};" : "=l"(d) : "f"(x));
    return d;
}
__device__ __forceinline__ float2 unpk(ull v)
{
    float2 r;
    asm("mov.b64 {%0, %1}, %2;" : "=f"(r.x), "=f"(r.y) : "l"(v));
    return r;
}

// ---------------- 128-bit global float4 reduction (sm_90+) -------------------
__device__ __forceinline__ void red_add_v4(float* p, float a, float b, float c, float d)
{
    asm volatile("red.global.add.v4.f32 [%0], {%1, %2, %3, %4};"
                 :: "l"(p), "f"(a), "f"(b), "f"(c), "f"(d) : "memory");
}

// ---------------- fused conv1 -> relu -> conv2 -> relu -> max ----------------
// one block per node, 512 threads. (R8 structure: FMA-bound, crossbar under floor)
__global__ __launch_bounds__(512, 2)
void conv_max_kernel(const float* __restrict__ x,
                     const float* __restrict__ w1, const float* __restrict__ b1,
                     const float* __restrict__ w2, const float* __restrict__ b2)
{
    __shared__ float xs[512];
    __shared__ float a_s[HID][512];
    __shared__ __align__(16) float ws2p[HID*3*16];
    __shared__ __align__(8)  float ws1p[8*3*2];
    __shared__ __align__(8)  float bs1[16];
    __shared__ __align__(16) float bs2[16];
    __shared__ float red[4][16];

    const int tid = threadIdx.x;
    const int n   = blockIdx.x;

    // --- phase 0: load x, stage weights, zero borders ------------------------
    {
        if (tid == 0) g_deg[n] = 0;

        if (tid < 502)
            xs[tid] = (tid == 0 || tid == 501) ? 0.f : x[n * FIN + (tid - 1)];

        if (tid < 32) a_s[tid >> 1][(tid & 1) ? 501 : 0] = 0.f;

        for (int i = tid; i < HID * 3 * HID; i += 512) {
            int ic  = i / 48;
            int rem = i - ic * 48;
            int t   = rem >> 4;
            int oc  = rem & 15;
            ws2p[i] = w2[oc * 48 + ic * 3 + t];
        }
        if (tid < 48) {
            int c = tid / 3, t = tid - c * 3;
            ws1p[((c >> 1) * 3 + t) * 2 + (c & 1)] = w1[tid];
        } else if (tid < 64)  bs1[tid - 48] = b1[tid - 48];
        else if (tid < 80)    bs2[tid - 64] = b2[tid - 64];
    }
    __syncthreads();

    // --- phase 1: conv1 (FFMA2 over channel pairs) + relu into a_s -----------
    if (tid < FIN) {
        const ull dm = dup2(xs[tid]);
        const ull d0 = dup2(xs[tid + 1]);
        const ull dp = dup2(xs[tid + 2]);
        #pragma unroll
        for (int cp = 0; cp < 8; cp++) {
            ull acc = *reinterpret_cast<const ull*>(&bs1[2 * cp]);
            acc = fma2(*reinterpret_cast<const ull*>(&ws1p[(cp * 3 + 0) * 2]), dm, acc);
            acc = fma2(*reinterpret_cast<const ull*>(&ws1p[(cp * 3 + 1) * 2]), d0, acc);
            acc = fma2(*reinterpret_cast<const ull*>(&ws1p[(cp * 3 + 2) * 2]), dp, acc);
            const float2 u = unpk(acc);
            a_s[2 * cp + 0][tid + 1] = fmaxf(u.x, 0.f);
            a_s[2 * cp + 1][tid + 1] = fmaxf(u.y, 0.f);
        }
    }
    __syncthreads();

    // --- phase 2: conv2 (FFMA2 packed over oc-pairs) + relu + max ------------
    {
        const int g  = tid >> 7;
        const int pg = tid & 127;
        float mx0 = -1e30f, mx1 = -1e30f, mx2 = -1e30f, mx3 = -1e30f;

        if (pg < 125) {
            const int p0 = pg << 2;
            const ull b01 = *reinterpret_cast<const ull*>(&bs2[4 * g]);
            const ull b23 = *reinterpret_cast<const ull*>(&bs2[4 * g + 2]);
            ull acc[4][2];
            #pragma unroll
            for (int r = 0; r < 4; r++) { acc[r][0] = b01; acc[r][1] = b23; }

            #pragma unroll
            for (int ic = 0; ic < HID; ic++) {
                const float4 av0 = *reinterpret_cast<const float4*>(&a_s[ic][p0]);
                const float2 av1 = *reinterpret_cast<const float2*>(&a_s[ic][p0 + 4]);
                ull d[6];
                d[0] = dup2(av0.x); d[1] = dup2(av0.y); d[2] = dup2(av0.z);
                d[3] = dup2(av0.w); d[4] = dup2(av1.x); d[5] = dup2(av1.y);

                const ulonglong2 w0  = *reinterpret_cast<const ulonglong2*>(&ws2p[(ic * 3 + 0) * 16 + 4 * g]);
                const ulonglong2 w1v = *reinterpret_cast<const ulonglong2*>(&ws2p[(ic * 3 + 1) * 16 + 4 * g]);
                const ulonglong2 w2v = *reinterpret_cast<const ulonglong2*>(&ws2p[(ic * 3 + 2) * 16 + 4 * g]);

                #pragma unroll
                for (int r = 0; r < 4; r++) {
                    acc[r][0] = fma2(w0.x,  d[r],     acc[r][0]);
                    acc[r][1] = fma2(w0.y,  d[r],     acc[r][1]);
                    acc[r][0] = fma2(w1v.x, d[r + 1], acc[r][0]);
                    acc[r][1] = fma2(w1v.y, d[r + 1], acc[r][1]);
                    acc[r][0] = fma2(w2v.x, d[r + 2], acc[r][0]);
                    acc[r][1] = fma2(w2v.y, d[r + 2], acc[r][1]);
                }
            }
            #pragma unroll
            for (int r = 0; r < 4; r++) {
                const float2 u0 = unpk(acc[r][0]);
                const float2 u1 = unpk(acc[r][1]);
                mx0 = fmaxf(mx0, u0.x); mx1 = fmaxf(mx1, u0.y);
                mx2 = fmaxf(mx2, u1.x); mx3 = fmaxf(mx3, u1.y);
            }
        }
        #pragma unroll
        for (int off = 16; off; off >>= 1) {
            mx0 = fmaxf(mx0, __shfl_xor_sync(0xffffffffu, mx0, off));
            mx1 = fmaxf(mx1, __shfl_xor_sync(0xffffffffu, mx1, off));
            mx2 = fmaxf(mx2, __shfl_xor_sync(0xffffffffu, mx2, off));
            mx3 = fmaxf(mx3, __shfl_xor_sync(0xffffffffu, mx3, off));
        }
        const int lane = tid & 31;
        const int wig  = (tid >> 5) & 3;
        if (lane == 0) {
            red[wig][4 * g + 0] = mx0;
            red[wig][4 * g + 1] = mx1;
            red[wig][4 * g + 2] = mx2;
            red[wig][4 * g + 3] = mx3;
        }
        __syncthreads();
        if (tid < HID) {
            float m = fmaxf(fmaxf(red[0][tid], red[1][tid]),
                            fmaxf(red[2][tid], red[3][tid]));
            g_h0[n * HID + tid] = fmaxf(m, 0.f);
        }
    }
}

// ---------------- degree count (g_deg zeroed in conv_max) --------------------
__global__ void deg_count_kernel(const int* __restrict__ dst)
{
    int i = blockIdx.x * blockDim.x + threadIdx.x;
    if (i < NEDGE) atomicAdd(&g_deg[dst[i]], 1);
}

// ---------------- gcn1: dinv + linear + self-loop init -----------------------
__global__ void lin1_kernel(const float* __restrict__ W, const float* __restrict__ b)
{
    __shared__ float Ws[HID * HID];
    __shared__ float bs[HID];
    const int tid = threadIdx.x;
    if (tid < HID * HID) Ws[tid] = W[tid];
    if (tid < HID)       bs[tid] = b[tid];
    __syncthreads();

    const int i = blockIdx.x * blockDim.x + tid;
    if (i >= NNODES) return;

    float h[HID];
    const float4* hp = reinterpret_cast<const float4*>(&g_h0[i * HID]);
    #pragma unroll
    for (int q = 0; q < 4; q++) {
        float4 v = hp[q];
        h[q * 4 + 0] = v.x; h[q * 4 + 1] = v.y; h[q * 4 + 2] = v.z; h[q * 4 + 3] = v.w;
    }
    float acc[HID];
    #pragma unroll
    for (int c = 0; c < HID; c++) acc[c] = 0.f;
    #pragma unroll
    for (int in = 0; in < HID; in++) {
        const float hv = h[in];
        #pragma unroll
        for (int c = 0; c < HID; c++) acc[c] = fmaf(hv, Ws[in * HID + c], acc[c]);
    }
    const float di = rsqrtf((float)(g_deg[i] + 1));
    g_dinv[i] = di;
    const float d2 = di * di;
    #pragma unroll
    for (int c = 0; c < HID; c++) {
        g_lin1[i * HID + c] = acc[c];
        g_acc1[i * HID + c] = fmaf(d2, acc[c], bs[c]);
    }
}

// ---------------- gcn1: edge scatter (1 thread/edge, 4x red.v4.f32) ----------
__global__ void scatter1_kernel(const int* __restrict__ src, const int* __restrict__ dst)
{
    int e = blockIdx.x * blockDim.x + threadIdx.x;
    if (e >= NEDGE) return;
    const int s = src[e];
    const int d = dst[e];
    const float w = g_dinv[s] * g_dinv[d];
    const float4* vp = reinterpret_cast<const float4*>(&g_lin1[s * HID]);
    float* out = &g_acc1[d * HID];
    #pragma unroll
    for (int q = 0; q < 4; q++) {
        const float4 v = vp[q];
        red_add_v4(out + 4 * q, w * v.x, w * v.y, w * v.z, w * v.w);
    }
}

// ---------------- gcn2: relu + linear(16->3) + self-loop init ----------------
__global__ void lin2_kernel(const float* __restrict__ W, const float* __restrict__ b)
{
    __shared__ float Ws[HID * OUTC];
    __shared__ float bs[OUTC];
    const int tid = threadIdx.x;
    if (tid < HID * OUTC) Ws[tid] = W[tid];
    if (tid < OUTC)       bs[tid] = b[tid];
    __syncthreads();

    const int i = blockIdx.x * blockDim.x + tid;
    if (i >= NNODES) return;

    float h[HID];
    const float4* hp = reinterpret_cast<const float4*>(&g_acc1[i * HID]);
    #pragma unroll
    for (int q = 0; q < 4; q++) {
        float4 v = hp[q];
        h[q * 4 + 0] = fmaxf(v.x, 0.f); h[q * 4 + 1] = fmaxf(v.y, 0.f);
        h[q * 4 + 2] = fmaxf(v.z, 0.f); h[q * 4 + 3] = fmaxf(v.w, 0.f);
    }
    float acc[OUTC] = {0.f, 0.f, 0.f};
    #pragma unroll
    for (int in = 0; in < HID; in++) {
        const float hv = h[in];
        #pragma unroll
        for (int c = 0; c < OUTC; c++) acc[c] = fmaf(hv, Ws[in * OUTC + c], acc[c]);
    }
    const float di = g_dinv[i];
    const float d2 = di * di;
    #pragma unroll
    for (int c = 0; c < OUTC; c++) {
        g_lin2[i * 4 + c] = acc[c];
        g_acc2[i * 4 + c] = fmaf(d2, acc[c], bs[c]);
    }
    g_lin2[i * 4 + 3] = 0.f;
    g_acc2[i * 4 + 3] = 0.f;
}

// ---------------- gcn2: edge scatter (1 thread/edge, 1x red.v4.f32) ----------
__global__ void scatter2_kernel(const int* __restrict__ src, const int* __restrict__ dst)
{
    int e = blockIdx.x * blockDim.x + threadIdx.x;
    if (e >= NEDGE) return;
    const int s = src[e];
    const int d = dst[e];
    const float w = g_dinv[s] * g_dinv[d];
    const float4 v = *reinterpret_cast<const float4*>(&g_lin2[s * 4]);
    red_add_v4(&g_acc2[d * 4], w * v.x, w * v.y, w * v.z, 0.f);
}

// ---------------- log_softmax (fast-math intrinsics) -------------------------
__global__ void logsoftmax_kernel(float* __restrict__ out)
{
    int i = blockIdx.x * blockDim.x + threadIdx.x;
    if (i >= NNODES) return;
    const float z0 = g_acc2[i * 4 + 0];
    const float z1 = g_acc2[i * 4 + 1];
    const float z2 = g_acc2[i * 4 + 2];
    const float m  = fmaxf(z0, fmaxf(z1, z2));
    const float s  = __expf(z0 - m) + __expf(z1 - m) + __expf(z2 - m);
    const float l  = m + __logf(s);
    out[i * 3 + 0] = z0 - l;
    out[i * 3 + 1] = z1 - l;
    out[i * 3 + 2] = z2 - l;
}

// ---------------- launcher ---------------------------------------------------
extern "C" void kernel_launch(void* const* d_in, const int* in_sizes, int n_in,
                              void* d_out, int out_size)
{
    const float* x       = (const float*)d_in[0];
    const float* conv1_w = (const float*)d_in[1];
    const float* conv1_b = (const float*)d_in[2];
    const float* conv2_w = (const float*)d_in[3];
    const float* conv2_b = (const float*)d_in[4];
    const float* gcn1_w  = (const float*)d_in[5];
    const float* gcn1_b  = (const float*)d_in[6];
    const float* gcn2_w  = (const float*)d_in[7];
    const float* gcn2_b  = (const float*)d_in[8];
    const int*   edges   = (const int*)d_in[9];
    const int*   src     = edges;
    const int*   dst     = edges + NEDGE;
    float*       out     = (float*)d_out;

    conv_max_kernel<<<NNODES, 512>>>(x, conv1_w, conv1_b, conv2_w, conv2_b);

    deg_count_kernel<<<(NEDGE + 255) / 256, 256>>>(dst);

    lin1_kernel    <<<(NNODES + 255) / 256, 256>>>(gcn1_w, gcn1_b);
    scatter1_kernel<<<(NEDGE + 255) / 256, 256>>>(src, dst);

    lin2_kernel    <<<(NNODES + 255) / 256, 256>>>(gcn2_w, gcn2_b);
    scatter2_kernel<<<(NEDGE + 255) / 256, 256>>>(src, dst);

    logsoftmax_kernel<<<(NNODES + 255) / 256, 256>>>(out);
}

// round 11
// speedup vs baseline: 1.6473x; 1.0006x over previous
#include <cuda_runtime.h>
#include <math.h>

#define NNODES 30000
#define FIN    500
#define HID    16
#define OUTC   3
#define NEDGE  960000

typedef unsigned long long ull;

// ---------------- scratch (static device arrays; no allocation) -------------
__device__ float g_h0  [NNODES * HID];
__device__ float g_lin1[NNODES * HID];
__device__ float g_acc1[NNODES * HID];
__device__ float g_lin2[NNODES * 4];
__device__ float g_acc2[NNODES * 4];
__device__ int   g_deg [NNODES];
__device__ float g_dinv[NNODES];

// ---------------- f32x2 packed-FMA helpers (sm_103a FFMA2) ------------------
__device__ __forceinline__ ull fma2(ull a, ull b, ull c)
{
    ull d;
    asm("fma.rn.f32x2 %0, %1, %2, %3;" : "=l"(d) : "l"(a), "l"(b), "l"(c));
    return d;
}
__device__ __forceinline__ ull dup2(float x)
{
    ull d;
    asm("mov.b64 %0, {%1, %1};" : "=l"(d) : "f"(x));
    return d;
}
__device__ __forceinline__ float2 unpk(ull v)
{
    float2 r;
    asm("mov.b64 {%0, %1}, %2;" : "=f"(r.x), "=f"(r.y) : "l"(v));
    return r;
}

// ---------------- 128-bit global float4 reduction (sm_90+) -------------------
__device__ __forceinline__ void red_add_v4(float* p, float a, float b, float c, float d)
{
    asm volatile("red.global.add.v4.f32 [%0], {%1, %2, %3, %4};"
                 :: "l"(p), "f"(a), "f"(b), "f"(c), "f"(d) : "memory");
}

// ---------------- fused conv1 -> relu -> conv2 -> relu -> max ----------------
// one block per node, 512 threads. (R8 structure: FMA-bound, crossbar under floor)
__global__ __launch_bounds__(512, 2)
void conv_max_kernel(const float* __restrict__ x,
                     const float* __restrict__ w1, const float* __restrict__ b1,
                     const float* __restrict__ w2, const float* __restrict__ b2)
{
    __shared__ float xs[512];
    __shared__ float a_s[HID][512];
    __shared__ __align__(16) float ws2p[HID*3*16];
    __shared__ __align__(8)  float ws1p[8*3*2];
    __shared__ __align__(8)  float bs1[16];
    __shared__ __align__(16) float bs2[16];
    __shared__ float red[4][16];

    const int tid = threadIdx.x;
    const int n   = blockIdx.x;

    // --- phase 0: load x, stage weights, zero borders ------------------------
    {
        if (tid == 0) g_deg[n] = 0;

        if (tid < 502)
            xs[tid] = (tid == 0 || tid == 501) ? 0.f : x[n * FIN + (tid - 1)];

        if (tid < 32) a_s[tid >> 1][(tid & 1) ? 501 : 0] = 0.f;

        for (int i = tid; i < HID * 3 * HID; i += 512) {
            int ic  = i / 48;
            int rem = i - ic * 48;
            int t   = rem >> 4;
            int oc  = rem & 15;
            ws2p[i] = w2[oc * 48 + ic * 3 + t];
        }
        if (tid < 48) {
            int c = tid / 3, t = tid - c * 3;
            ws1p[((c >> 1) * 3 + t) * 2 + (c & 1)] = w1[tid];
        } else if (tid < 64)  bs1[tid - 48] = b1[tid - 48];
        else if (tid < 80)    bs2[tid - 64] = b2[tid - 64];
    }
    __syncthreads();

    // --- phase 1: conv1 (FFMA2 over channel pairs) + relu into a_s -----------
    if (tid < FIN) {
        const ull dm = dup2(xs[tid]);
        const ull d0 = dup2(xs[tid + 1]);
        const ull dp = dup2(xs[tid + 2]);
        #pragma unroll
        for (int cp = 0; cp < 8; cp++) {
            ull acc = *reinterpret_cast<const ull*>(&bs1[2 * cp]);
            acc = fma2(*reinterpret_cast<const ull*>(&ws1p[(cp * 3 + 0) * 2]), dm, acc);
            acc = fma2(*reinterpret_cast<const ull*>(&ws1p[(cp * 3 + 1) * 2]), d0, acc);
            acc = fma2(*reinterpret_cast<const ull*>(&ws1p[(cp * 3 + 2) * 2]), dp, acc);
            const float2 u = unpk(acc);
            a_s[2 * cp + 0][tid + 1] = fmaxf(u.x, 0.f);
            a_s[2 * cp + 1][tid + 1] = fmaxf(u.y, 0.f);
        }
    }
    __syncthreads();

    // --- phase 2: conv2 (FFMA2 packed over oc-pairs) + relu + max ------------
    {
        const int g  = tid >> 7;
        const int pg = tid & 127;
        float mx0 = -1e30f, mx1 = -1e30f, mx2 = -1e30f, mx3 = -1e30f;

        if (pg < 125) {
            const int p0 = pg << 2;
            const ull b01 = *reinterpret_cast<const ull*>(&bs2[4 * g]);
            const ull b23 = *reinterpret_cast<const ull*>(&bs2[4 * g + 2]);
            ull acc[4][2];
            #pragma unroll
            for (int r = 0; r < 4; r++) { acc[r][0] = b01; acc[r][1] = b23; }

            #pragma unroll
            for (int ic = 0; ic < HID; ic++) {
                const float4 av0 = *reinterpret_cast<const float4*>(&a_s[ic][p0]);
                const float2 av1 = *reinterpret_cast<const float2*>(&a_s[ic][p0 + 4]);
                ull d[6];
                d[0] = dup2(av0.x); d[1] = dup2(av0.y); d[2] = dup2(av0.z);
                d[3] = dup2(av0.w); d[4] = dup2(av1.x); d[5] = dup2(av1.y);

                const ulonglong2 w0  = *reinterpret_cast<const ulonglong2*>(&ws2p[(ic * 3 + 0) * 16 + 4 * g]);
                const ulonglong2 w1v = *reinterpret_cast<const ulonglong2*>(&ws2p[(ic * 3 + 1) * 16 + 4 * g]);
                const ulonglong2 w2v = *reinterpret_cast<const ulonglong2*>(&ws2p[(ic * 3 + 2) * 16 + 4 * g]);

                #pragma unroll
                for (int r = 0; r < 4; r++) {
                    acc[r][0] = fma2(w0.x,  d[r],     acc[r][0]);
                    acc[r][1] = fma2(w0.y,  d[r],     acc[r][1]);
                    acc[r][0] = fma2(w1v.x, d[r + 1], acc[r][0]);
                    acc[r][1] = fma2(w1v.y, d[r + 1], acc[r][1]);
                    acc[r][0] = fma2(w2v.x, d[r + 2], acc[r][0]);
                    acc[r][1] = fma2(w2v.y, d[r + 2], acc[r][1]);
                }
            }
            #pragma unroll
            for (int r = 0; r < 4; r++) {
                const float2 u0 = unpk(acc[r][0]);
                const float2 u1 = unpk(acc[r][1]);
                mx0 = fmaxf(mx0, u0.x); mx1 = fmaxf(mx1, u0.y);
                mx2 = fmaxf(mx2, u1.x); mx3 = fmaxf(mx3, u1.y);
            }
        }
        #pragma unroll
        for (int off = 16; off; off >>= 1) {
            mx0 = fmaxf(mx0, __shfl_xor_sync(0xffffffffu, mx0, off));
            mx1 = fmaxf(mx1, __shfl_xor_sync(0xffffffffu, mx1, off));
            mx2 = fmaxf(mx2, __shfl_xor_sync(0xffffffffu, mx2, off));
            mx3 = fmaxf(mx3, __shfl_xor_sync(0xffffffffu, mx3, off));
        }
        const int lane = tid & 31;
        const int wig  = (tid >> 5) & 3;
        if (lane == 0) {
            red[wig][4 * g + 0] = mx0;
            red[wig][4 * g + 1] = mx1;
            red[wig][4 * g + 2] = mx2;
            red[wig][4 * g + 3] = mx3;
        }
        __syncthreads();
        if (tid < HID) {
            float m = fmaxf(fmaxf(red[0][tid], red[1][tid]),
                            fmaxf(red[2][tid], red[3][tid]));
            g_h0[n * HID + tid] = fmaxf(m, 0.f);
        }
    }
}

// ---------------- degree count (g_deg zeroed in conv_max) --------------------
__global__ void deg_count_kernel(const int* __restrict__ dst)
{
    int i = blockIdx.x * blockDim.x + threadIdx.x;
    if (i < NEDGE) atomicAdd(&g_deg[dst[i]], 1);
}

// ---------------- gcn1: dinv + linear + self-loop init -----------------------
__global__ void lin1_kernel(const float* __restrict__ W, const float* __restrict__ b)
{
    __shared__ float Ws[HID * HID];
    __shared__ float bs[HID];
    const int tid = threadIdx.x;
    if (tid < HID * HID) Ws[tid] = W[tid];
    if (tid < HID)       bs[tid] = b[tid];
    __syncthreads();

    const int i = blockIdx.x * blockDim.x + tid;
    if (i >= NNODES) return;

    float h[HID];
    const float4* hp = reinterpret_cast<const float4*>(&g_h0[i * HID]);
    #pragma unroll
    for (int q = 0; q < 4; q++) {
        float4 v = hp[q];
        h[q * 4 + 0] = v.x; h[q * 4 + 1] = v.y; h[q * 4 + 2] = v.z; h[q * 4 + 3] = v.w;
    }
    float acc[HID];
    #pragma unroll
    for (int c = 0; c < HID; c++) acc[c] = 0.f;
    #pragma unroll
    for (int in = 0; in < HID; in++) {
        const float hv = h[in];
        #pragma unroll
        for (int c = 0; c < HID; c++) acc[c] = fmaf(hv, Ws[in * HID + c], acc[c]);
    }
    const float di = rsqrtf((float)(g_deg[i] + 1));
    g_dinv[i] = di;
    const float d2 = di * di;
    #pragma unroll
    for (int c = 0; c < HID; c++) {
        g_lin1[i * HID + c] = acc[c];
        g_acc1[i * HID + c] = fmaf(d2, acc[c], bs[c]);
    }
}

// ---------------- gcn1: edge scatter (1 thread/edge, 4x red.v4.f32) ----------
__global__ void scatter1_kernel(const int* __restrict__ src, const int* __restrict__ dst)
{
    int e = blockIdx.x * blockDim.x + threadIdx.x;
    if (e >= NEDGE) return;
    const int s = src[e];
    const int d = dst[e];
    const float w = g_dinv[s] * g_dinv[d];
    const float4* vp = reinterpret_cast<const float4*>(&g_lin1[s * HID]);
    float* out = &g_acc1[d * HID];
    #pragma unroll
    for (int q = 0; q < 4; q++) {
        const float4 v = vp[q];
        red_add_v4(out + 4 * q, w * v.x, w * v.y, w * v.z, w * v.w);
    }
}

// ---------------- gcn2: relu + linear(16->3) + self-loop init ----------------
__global__ void lin2_kernel(const float* __restrict__ W, const float* __restrict__ b)
{
    __shared__ float Ws[HID * OUTC];
    __shared__ float bs[OUTC];
    const int tid = threadIdx.x;
    if (tid < HID * OUTC) Ws[tid] = W[tid];
    if (tid < OUTC)       bs[tid] = b[tid];
    __syncthreads();

    const int i = blockIdx.x * blockDim.x + tid;
    if (i >= NNODES) return;

    float h[HID];
    const float4* hp = reinterpret_cast<const float4*>(&g_acc1[i * HID]);
    #pragma unroll
    for (int q = 0; q < 4; q++) {
        float4 v = hp[q];
        h[q * 4 + 0] = fmaxf(v.x, 0.f); h[q * 4 + 1] = fmaxf(v.y, 0.f);
        h[q * 4 + 2] = fmaxf(v.z, 0.f); h[q * 4 + 3] = fmaxf(v.w, 0.f);
    }
    float acc[OUTC] = {0.f, 0.f, 0.f};
    #pragma unroll
    for (int in = 0; in < HID; in++) {
        const float hv = h[in];
        #pragma unroll
        for (int c = 0; c < OUTC; c++) acc[c] = fmaf(hv, Ws[in * OUTC + c], acc[c]);
    }
    const float di = g_dinv[i];
    const float d2 = di * di;
    #pragma unroll
    for (int c = 0; c < OUTC; c++) {
        g_lin2[i * 4 + c] = acc[c];
        g_acc2[i * 4 + c] = fmaf(d2, acc[c], bs[c]);
    }
    g_lin2[i * 4 + 3] = 0.f;
    g_acc2[i * 4 + 3] = 0.f;
}

// ---------------- gcn2: edge scatter (1 thread/edge, 1x red.v4.f32) ----------
__global__ void scatter2_kernel(const int* __restrict__ src, const int* __restrict__ dst)
{
    int e = blockIdx.x * blockDim.x + threadIdx.x;
    if (e >= NEDGE) return;
    const int s = src[e];
    const int d = dst[e];
    const float w = g_dinv[s] * g_dinv[d];
    const float4 v = *reinterpret_cast<const float4*>(&g_lin2[s * 4]);
    red_add_v4(&g_acc2[d * 4], w * v.x, w * v.y, w * v.z, 0.f);
}

// ---------------- log_softmax (fast-math intrinsics) -------------------------
__global__ void logsoftmax_kernel(float* __restrict__ out)
{
    int i = blockIdx.x * blockDim.x + threadIdx.x;
    if (i >= NNODES) return;
    const float z0 = g_acc2[i * 4 + 0];
    const float z1 = g_acc2[i * 4 + 1];
    const float z2 = g_acc2[i * 4 + 2];
    const float m  = fmaxf(z0, fmaxf(z1, z2));
    const float s  = __expf(z0 - m) + __expf(z1 - m) + __expf(z2 - m);
    const float l  = m + __logf(s);
    out[i * 3 + 0] = z0 - l;
    out[i * 3 + 1] = z1 - l;
    out[i * 3 + 2] = z2 - l;
}

// ---------------- launcher ---------------------------------------------------
extern "C" void kernel_launch(void* const* d_in, const int* in_sizes, int n_in,
                              void* d_out, int out_size)
{
    const float* x       = (const float*)d_in[0];
    const float* conv1_w = (const float*)d_in[1];
    const float* conv1_b = (const float*)d_in[2];
    const float* conv2_w = (const float*)d_in[3];
    const float* conv2_b = (const float*)d_in[4];
    const float* gcn1_w  = (const float*)d_in[5];
    const float* gcn1_b  = (const float*)d_in[6];
    const float* gcn2_w  = (const float*)d_in[7];
    const float* gcn2_b  = (const float*)d_in[8];
    const int*   edges   = (const int*)d_in[9];
    const int*   src     = edges;
    const int*   dst     = edges + NEDGE;
    float*       out     = (float*)d_out;

    conv_max_kernel<<<NNODES, 512>>>(x, conv1_w, conv1_b, conv2_w, conv2_b);

    deg_count_kernel<<<(NEDGE + 255) / 256, 256>>>(dst);

    lin1_kernel    <<<(NNODES + 255) / 256, 256>>>(gcn1_w, gcn1_b);
    scatter1_kernel<<<(NEDGE + 255) / 256, 256>>>(src, dst);

    lin2_kernel    <<<(NNODES + 255) / 256, 256>>>(gcn2_w, gcn2_b);
    scatter2_kernel<<<(NEDGE + 255) / 256, 256>>>(src, dst);

    logsoftmax_kernel<<<(NNODES + 255) / 256, 256>>>(out);
}

// round 12
// speedup vs baseline: 1.8078x; 1.0975x over previous
#include <cuda_runtime.h>
#include <math.h>

#define NNODES 30000
#define FIN    500
#define HID    16
#define OUTC   3
#define NEDGE  960000

typedef unsigned long long ull;

// ---------------- scratch (static device arrays; no allocation) -------------
__device__ float g_h0  [NNODES * HID];
__device__ float g_lin1[NNODES * HID];
__device__ float g_acc1[NNODES * HID];
__device__ float g_lin2[NNODES * 4];
__device__ float g_acc2[NNODES * 4];
__device__ int   g_deg [NNODES];
__device__ float g_dinv[NNODES];

// ---------------- f32x2 packed-FMA helpers (sm_103a FFMA2) ------------------
__device__ __forceinline__ ull fma2(ull a, ull b, ull c)
{
    ull d;
    asm("fma.rn.f32x2 %0, %1, %2, %3;" : "=l"(d) : "l"(a), "l"(b), "l"(c));
    return d;
}
__device__ __forceinline__ ull dup2(float x)
{
    ull d;
    asm("mov.b64 %0, {%1, %1};" : "=l"(d) : "f"(x));
    return d;
}
__device__ __forceinline__ float2 unpk(ull v)
{
    float2 r;
    asm("mov.b64 {%0, %1}, %2;" : "=f"(r.x), "=f"(r.y) : "l"(v));
    return r;
}

// ---------------- 128-bit global float4 reduction (sm_90+) -------------------
__device__ __forceinline__ void red_add_v4(float* p, float a, float b, float c, float d)
{
    asm volatile("red.global.add.v4.f32 [%0], {%1, %2, %3, %4};"
                 :: "l"(p), "f"(a), "f"(b), "f"(c), "f"(d) : "memory");
}

// ---------------- conv smem: TWO nodes per block ------------------------------
// node slot k occupies columns [512k, 512k+512): a[p] at col 512k + p + 1,
// borders (cols 512k+0, 512k+501) zeroed. xs[512k + i] = x[i-1], pads 0.
struct ConvSm {
    float xs [1024];
    float a_s[HID][1024];
    float ws2p[HID * 3 * 16];   // [ic][tap][oc] transposed conv2 weights
    float ws1p[8 * 3 * 2];      // conv1 weights packed over channel pairs
    float bs1[16];
    float bs2[16];
    float red[4][16];
};
#define CONV_SMEM_BYTES ((int)sizeof(ConvSm))

// ---------------- fused conv1 -> relu -> conv2 -> relu -> max (2 nodes/blk) ---
__global__ __launch_bounds__(512, 2)
void conv_max_kernel(const float* __restrict__ x,
                     const float* __restrict__ w1, const float* __restrict__ b1,
                     const float* __restrict__ w2, const float* __restrict__ b2)
{
    extern __shared__ __align__(16) char smem_raw[];
    ConvSm* sm = reinterpret_cast<ConvSm*>(smem_raw);

    const int tid = threadIdx.x;
    const int n0  = blockIdx.x * 2;       // first of the two nodes

    // --- phase 0: load x (both nodes), stage weights, zero borders -----------
    {
        if (tid < 2) g_deg[n0 + tid] = 0;

        #pragma unroll
        for (int it = 0; it < 2; it++) {
            const int idx = tid + (it << 9);       // 0..1023
            const int k   = idx >> 9;
            const int i   = idx & 511;
            sm->xs[idx] = (i >= 1 && i <= 500) ? x[(n0 + k) * FIN + (i - 1)] : 0.f;
        }

        // borders: a_s[ch][512k + {0,501}] = 0  (16 ch x 2 borders x 2 nodes)
        if (tid < 64) {
            const int ch = tid >> 2;
            const int w_ = tid & 3;
            const int col = ((w_ & 1) ? 501 : 0) + ((w_ >> 1) << 9);
            sm->a_s[ch][col] = 0.f;
        }

        // ws2p[(ic*3 + t)*16 + oc] = w2[oc*48 + ic*3 + t]
        for (int i = tid; i < HID * 3 * HID; i += 512) {
            int ic  = i / 48;
            int rem = i - ic * 48;
            int t   = rem >> 4;
            int oc  = rem & 15;
            sm->ws2p[i] = w2[oc * 48 + ic * 3 + t];
        }
        if (tid < 48) {
            int c = tid / 3, t = tid - c * 3;
            sm->ws1p[((c >> 1) * 3 + t) * 2 + (c & 1)] = w1[tid];
        } else if (tid < 64)  sm->bs1[tid - 48] = b1[tid - 48];
        else if (tid < 80)    sm->bs2[tid - 64] = b2[tid - 64];
    }
    __syncthreads();

    // --- phase 1: conv1 (FFMA2 over channel pairs) + relu, both nodes --------
    #pragma unroll
    for (int it = 0; it < 2; it++) {
        const int idx = tid + (it << 9);
        const int k   = idx >> 9;
        const int p   = idx & 511;
        if (p < FIN) {
            const int b = k << 9;
            const ull dm = dup2(sm->xs[b + p]);
            const ull d0 = dup2(sm->xs[b + p + 1]);
            const ull dp = dup2(sm->xs[b + p + 2]);
            #pragma unroll
            for (int cp = 0; cp < 8; cp++) {
                ull acc = *reinterpret_cast<const ull*>(&sm->bs1[2 * cp]);
                acc = fma2(*reinterpret_cast<const ull*>(&sm->ws1p[(cp * 3 + 0) * 2]), dm, acc);
                acc = fma2(*reinterpret_cast<const ull*>(&sm->ws1p[(cp * 3 + 1) * 2]), d0, acc);
                acc = fma2(*reinterpret_cast<const ull*>(&sm->ws1p[(cp * 3 + 2) * 2]), dp, acc);
                const float2 u = unpk(acc);
                sm->a_s[2 * cp + 0][b + p + 1] = fmaxf(u.x, 0.f);
                sm->a_s[2 * cp + 1][b + p + 1] = fmaxf(u.y, 0.f);
            }
        }
    }
    __syncthreads();

    // --- phase 2: conv2 (FFMA2 oc-pair packed) + relu + max, per node --------
    const int g  = tid >> 7;     // oc group: channels 4g..4g+3 (warp-uniform)
    const int pg = tid & 127;
    const int lane = tid & 31;
    const int wig  = (tid >> 5) & 3;

    #pragma unroll
    for (int k = 0; k < 2; k++) {
        if (k == 1) __syncthreads();   // separate node-0 red[] reads from node-1 writes

        float mx0 = -1e30f, mx1 = -1e30f, mx2 = -1e30f, mx3 = -1e30f;

        if (pg < 125) {
            const int p0 = (pg << 2) + (k << 9);
            const ull b01 = *reinterpret_cast<const ull*>(&sm->bs2[4 * g]);
            const ull b23 = *reinterpret_cast<const ull*>(&sm->bs2[4 * g + 2]);
            ull acc[4][2];
            #pragma unroll
            for (int r = 0; r < 4; r++) { acc[r][0] = b01; acc[r][1] = b23; }

            #pragma unroll
            for (int ic = 0; ic < HID; ic++) {
                const float4 av0 = *reinterpret_cast<const float4*>(&sm->a_s[ic][p0]);
                const float2 av1 = *reinterpret_cast<const float2*>(&sm->a_s[ic][p0 + 4]);
                ull d[6];
                d[0] = dup2(av0.x); d[1] = dup2(av0.y); d[2] = dup2(av0.z);
                d[3] = dup2(av0.w); d[4] = dup2(av1.x); d[5] = dup2(av1.y);

                const ulonglong2 w0  = *reinterpret_cast<const ulonglong2*>(&sm->ws2p[(ic * 3 + 0) * 16 + 4 * g]);
                const ulonglong2 w1v = *reinterpret_cast<const ulonglong2*>(&sm->ws2p[(ic * 3 + 1) * 16 + 4 * g]);
                const ulonglong2 w2v = *reinterpret_cast<const ulonglong2*>(&sm->ws2p[(ic * 3 + 2) * 16 + 4 * g]);

                #pragma unroll
                for (int r = 0; r < 4; r++) {
                    acc[r][0] = fma2(w0.x,  d[r],     acc[r][0]);
                    acc[r][1] = fma2(w0.y,  d[r],     acc[r][1]);
                    acc[r][0] = fma2(w1v.x, d[r + 1], acc[r][0]);
                    acc[r][1] = fma2(w1v.y, d[r + 1], acc[r][1]);
                    acc[r][0] = fma2(w2v.x, d[r + 2], acc[r][0]);
                    acc[r][1] = fma2(w2v.y, d[r + 2], acc[r][1]);
                }
            }
            #pragma unroll
            for (int r = 0; r < 4; r++) {
                const float2 u0 = unpk(acc[r][0]);
                const float2 u1 = unpk(acc[r][1]);
                mx0 = fmaxf(mx0, u0.x); mx1 = fmaxf(mx1, u0.y);
                mx2 = fmaxf(mx2, u1.x); mx3 = fmaxf(mx3, u1.y);
            }
        }
        #pragma unroll
        for (int off = 16; off; off >>= 1) {
            mx0 = fmaxf(mx0, __shfl_xor_sync(0xffffffffu, mx0, off));
            mx1 = fmaxf(mx1, __shfl_xor_sync(0xffffffffu, mx1, off));
            mx2 = fmaxf(mx2, __shfl_xor_sync(0xffffffffu, mx2, off));
            mx3 = fmaxf(mx3, __shfl_xor_sync(0xffffffffu, mx3, off));
        }
        if (lane == 0) {
            sm->red[wig][4 * g + 0] = mx0;
            sm->red[wig][4 * g + 1] = mx1;
            sm->red[wig][4 * g + 2] = mx2;
            sm->red[wig][4 * g + 3] = mx3;
        }
        __syncthreads();
        if (tid < HID) {
            float m = fmaxf(fmaxf(sm->red[0][tid], sm->red[1][tid]),
                            fmaxf(sm->red[2][tid], sm->red[3][tid]));
            g_h0[(n0 + k) * HID + tid] = fmaxf(m, 0.f);
        }
    }
}

// ---------------- degree count (g_deg zeroed in conv_max) --------------------
__global__ void deg_count_kernel(const int* __restrict__ dst)
{
    int i = blockIdx.x * blockDim.x + threadIdx.x;
    if (i < NEDGE) atomicAdd(&g_deg[dst[i]], 1);
}

// ---------------- gcn1: dinv + linear + self-loop init -----------------------
__global__ void lin1_kernel(const float* __restrict__ W, const float* __restrict__ b)
{
    __shared__ float Ws[HID * HID];
    __shared__ float bs[HID];
    const int tid = threadIdx.x;
    if (tid < HID * HID) Ws[tid] = W[tid];
    if (tid < HID)       bs[tid] = b[tid];
    __syncthreads();

    const int i = blockIdx.x * blockDim.x + tid;
    if (i >= NNODES) return;

    float h[HID];
    const float4* hp = reinterpret_cast<const float4*>(&g_h0[i * HID]);
    #pragma unroll
    for (int q = 0; q < 4; q++) {
        float4 v = hp[q];
        h[q * 4 + 0] = v.x; h[q * 4 + 1] = v.y; h[q * 4 + 2] = v.z; h[q * 4 + 3] = v.w;
    }
    float acc[HID];
    #pragma unroll
    for (int c = 0; c < HID; c++) acc[c] = 0.f;
    #pragma unroll
    for (int in = 0; in < HID; in++) {
        const float hv = h[in];
        #pragma unroll
        for (int c = 0; c < HID; c++) acc[c] = fmaf(hv, Ws[in * HID + c], acc[c]);
    }
    const float di = rsqrtf((float)(g_deg[i] + 1));
    g_dinv[i] = di;
    const float d2 = di * di;
    #pragma unroll
    for (int c = 0; c < HID; c++) {
        g_lin1[i * HID + c] = acc[c];
        g_acc1[i * HID + c] = fmaf(d2, acc[c], bs[c]);
    }
}

// ---------------- gcn1: edge scatter (1 thread/edge, 4x red.v4.f32) ----------
__global__ void scatter1_kernel(const int* __restrict__ src, const int* __restrict__ dst)
{
    int e = blockIdx.x * blockDim.x + threadIdx.x;
    if (e >= NEDGE) return;
    const int s = src[e];
    const int d = dst[e];
    const float w = g_dinv[s] * g_dinv[d];
    const float4* vp = reinterpret_cast<const float4*>(&g_lin1[s * HID]);
    float* out = &g_acc1[d * HID];
    #pragma unroll
    for (int q = 0; q < 4; q++) {
        const float4 v = vp[q];
        red_add_v4(out + 4 * q, w * v.x, w * v.y, w * v.z, w * v.w);
    }
}

// ---------------- gcn2: relu + linear(16->3) + self-loop init ----------------
__global__ void lin2_kernel(const float* __restrict__ W, const float* __restrict__ b)
{
    __shared__ float Ws[HID * OUTC];
    __shared__ float bs[OUTC];
    const int tid = threadIdx.x;
    if (tid < HID * OUTC) Ws[tid] = W[tid];
    if (tid < OUTC)       bs[tid] = b[tid];
    __syncthreads();

    const int i = blockIdx.x * blockDim.x + tid;
    if (i >= NNODES) return;

    float h[HID];
    const float4* hp = reinterpret_cast<const float4*>(&g_acc1[i * HID]);
    #pragma unroll
    for (int q = 0; q < 4; q++) {
        float4 v = hp[q];
        h[q * 4 + 0] = fmaxf(v.x, 0.f); h[q * 4 + 1] = fmaxf(v.y, 0.f);
        h[q * 4 + 2] = fmaxf(v.z, 0.f); h[q * 4 + 3] = fmaxf(v.w, 0.f);
    }
    float acc[OUTC] = {0.f, 0.f, 0.f};
    #pragma unroll
    for (int in = 0; in < HID; in++) {
        const float hv = h[in];
        #pragma unroll
        for (int c = 0; c < OUTC; c++) acc[c] = fmaf(hv, Ws[in * OUTC + c], acc[c]);
    }
    const float di = g_dinv[i];
    const float d2 = di * di;
    #pragma unroll
    for (int c = 0; c < OUTC; c++) {
        g_lin2[i * 4 + c] = acc[c];
        g_acc2[i * 4 + c] = fmaf(d2, acc[c], bs[c]);
    }
    g_lin2[i * 4 + 3] = 0.f;
    g_acc2[i * 4 + 3] = 0.f;
}

// ---------------- gcn2: edge scatter (1 thread/edge, 1x red.v4.f32) ----------
__global__ void scatter2_kernel(const int* __restrict__ src, const int* __restrict__ dst)
{
    int e = blockIdx.x * blockDim.x + threadIdx.x;
    if (e >= NEDGE) return;
    const int s = src[e];
    const int d = dst[e];
    const float w = g_dinv[s] * g_dinv[d];
    const float4 v = *reinterpret_cast<const float4*>(&g_lin2[s * 4]);
    red_add_v4(&g_acc2[d * 4], w * v.x, w * v.y, w * v.z, 0.f);
}

// ---------------- log_softmax (fast-math intrinsics) -------------------------
__global__ void logsoftmax_kernel(float* __restrict__ out)
{
    int i = blockIdx.x * blockDim.x + threadIdx.x;
    if (i >= NNODES) return;
    const float z0 = g_acc2[i * 4 + 0];
    const float z1 = g_acc2[i * 4 + 1];
    const float z2 = g_acc2[i * 4 + 2];
    const float m  = fmaxf(z0, fmaxf(z1, z2));
    const float s  = __expf(z0 - m) + __expf(z1 - m) + __expf(z2 - m);
    const float l  = m + __logf(s);
    out[i * 3 + 0] = z0 - l;
    out[i * 3 + 1] = z1 - l;
    out[i * 3 + 2] = z2 - l;
}

// ---------------- launcher ---------------------------------------------------
extern "C" void kernel_launch(void* const* d_in, const int* in_sizes, int n_in,
                              void* d_out, int out_size)
{
    const float* x       = (const float*)d_in[0];
    const float* conv1_w = (const float*)d_in[1];
    const float* conv1_b = (const float*)d_in[2];
    const float* conv2_w = (const float*)d_in[3];
    const float* conv2_b = (const float*)d_in[4];
    const float* gcn1_w  = (const float*)d_in[5];
    const float* gcn1_b  = (const float*)d_in[6];
    const float* gcn2_w  = (const float*)d_in[7];
    const float* gcn2_b  = (const float*)d_in[8];
    const int*   edges   = (const int*)d_in[9];
    const int*   src     = edges;
    const int*   dst     = edges + NEDGE;
    float*       out     = (float*)d_out;

    cudaFuncSetAttribute(conv_max_kernel,
                         cudaFuncAttributeMaxDynamicSharedMemorySize,
                         CONV_SMEM_BYTES);

    conv_max_kernel<<<NNODES / 2, 512, CONV_SMEM_BYTES>>>(x, conv1_w, conv1_b, conv2_w, conv2_b);

    deg_count_kernel<<<(NEDGE + 255) / 256, 256>>>(dst);

    lin1_kernel    <<<(NNODES + 255) / 256, 256>>>(gcn1_w, gcn1_b);
    scatter1_kernel<<<(NEDGE + 255) / 256, 256>>>(src, dst);

    lin2_kernel    <<<(NNODES + 255) / 256, 256>>>(gcn2_w, gcn2_b);
    scatter2_kernel<<<(NEDGE + 255) / 256, 256>>>(src, dst);

    logsoftmax_kernel<<<(NNODES + 255) / 256, 256>>>(out);
}

// round 13
// speedup vs baseline: 1.8223x; 1.0080x over previous
#include <cuda_runtime.h>
#include <math.h>

#define NNODES 30000
#define FIN    500
#define HID    16
#define OUTC   3
#define NEDGE  960000

#define NPB    3            // nodes per conv block
#define NGRID  (NNODES / NPB)   // 10000

typedef unsigned long long ull;

// ---------------- scratch (static device arrays; no allocation) -------------
__device__ float g_h0  [NNODES * HID];
__device__ float g_lin1[NNODES * HID];
__device__ float g_acc1[NNODES * HID];
__device__ float g_lin2[NNODES * 4];
__device__ float g_acc2[NNODES * 4];
__device__ int   g_deg [NNODES];
__device__ float g_dinv[NNODES];

// ---------------- f32x2 packed-FMA helpers (sm_103a FFMA2) ------------------
__device__ __forceinline__ ull fma2(ull a, ull b, ull c)
{
    ull d;
    asm("fma.rn.f32x2 %0, %1, %2, %3;" : "=l"(d) : "l"(a), "l"(b), "l"(c));
    return d;
}
__device__ __forceinline__ ull dup2(float x)
{
    ull d;
    asm("mov.b64 %0, {%1, %1};" : "=l"(d) : "f"(x));
    return d;
}
__device__ __forceinline__ float2 unpk(ull v)
{
    float2 r;
    asm("mov.b64 {%0, %1}, %2;" : "=f"(r.x), "=f"(r.y) : "l"(v));
    return r;
}

// ---------------- 128-bit global float4 reduction (sm_90+) -------------------
__device__ __forceinline__ void red_add_v4(float* p, float a, float b, float c, float d)
{
    asm volatile("red.global.add.v4.f32 [%0], {%1, %2, %3, %4};"
                 :: "l"(p), "f"(a), "f"(b), "f"(c), "f"(d) : "memory");
}

// ---------------- conv smem: THREE nodes per block ----------------------------
// node slot k occupies columns [512k, 512k+512): a[p] at col 512k + p + 1,
// borders (cols 512k+0, 512k+501) zeroed. xs[512k + i] = x[i-1], pads 0.
struct ConvSm {
    float xs [512 * NPB];
    float a_s[HID][512 * NPB];
    float ws2p[HID * 3 * 16];   // [ic][tap][oc] transposed conv2 weights
    float ws1p[8 * 3 * 2];      // conv1 weights packed over channel pairs
    float bs1[16];
    float bs2[16];
    float red[4][16];
};
#define CONV_SMEM_BYTES ((int)sizeof(ConvSm))

// ---------------- fused conv1 -> relu -> conv2 -> relu -> max (3 nodes/blk) ---
__global__ __launch_bounds__(512, 2)
void conv_max_kernel(const float* __restrict__ x,
                     const float* __restrict__ w1, const float* __restrict__ b1,
                     const float* __restrict__ w2, const float* __restrict__ b2)
{
    extern __shared__ __align__(16) char smem_raw[];
    ConvSm* sm = reinterpret_cast<ConvSm*>(smem_raw);

    const int tid = threadIdx.x;
    const int n0  = blockIdx.x * NPB;     // first of the NPB nodes

    // --- phase 0: load x (all nodes), stage weights, zero borders ------------
    {
        if (tid < NPB) g_deg[n0 + tid] = 0;

        #pragma unroll
        for (int it = 0; it < NPB; it++) {
            const int idx = tid + (it << 9);       // 0 .. 512*NPB-1
            const int k   = idx >> 9;
            const int i   = idx & 511;
            sm->xs[idx] = (i >= 1 && i <= 500) ? x[(n0 + k) * FIN + (i - 1)] : 0.f;
        }

        // borders: a_s[ch][512k + {0,501}] = 0  (16 ch x 2 borders x NPB nodes)
        if (tid < 32 * NPB) {
            const int k  = tid / 32;
            const int r  = tid - k * 32;
            const int ch = r >> 1;
            const int col = ((r & 1) ? 501 : 0) + (k << 9);
            sm->a_s[ch][col] = 0.f;
        }

        // ws2p[(ic*3 + t)*16 + oc] = w2[oc*48 + ic*3 + t]
        for (int i = tid; i < HID * 3 * HID; i += 512) {
            int ic  = i / 48;
            int rem = i - ic * 48;
            int t   = rem >> 4;
            int oc  = rem & 15;
            sm->ws2p[i] = w2[oc * 48 + ic * 3 + t];
        }
        if (tid >= 128 && tid < 176) {
            int j = tid - 128;
            int c = j / 3, t = j - c * 3;
            sm->ws1p[((c >> 1) * 3 + t) * 2 + (c & 1)] = w1[j];
        } else if (tid >= 176 && tid < 192) sm->bs1[tid - 176] = b1[tid - 176];
        else if (tid >= 192 && tid < 208)   sm->bs2[tid - 192] = b2[tid - 192];
    }
    __syncthreads();

    // --- phase 1: conv1 (FFMA2 over channel pairs) + relu, all nodes ---------
    #pragma unroll
    for (int it = 0; it < NPB; it++) {
        const int idx = tid + (it << 9);
        const int k   = idx >> 9;
        const int p   = idx & 511;
        if (p < FIN) {
            const int b = k << 9;
            const ull dm = dup2(sm->xs[b + p]);
            const ull d0 = dup2(sm->xs[b + p + 1]);
            const ull dp = dup2(sm->xs[b + p + 2]);
            #pragma unroll
            for (int cp = 0; cp < 8; cp++) {
                ull acc = *reinterpret_cast<const ull*>(&sm->bs1[2 * cp]);
                acc = fma2(*reinterpret_cast<const ull*>(&sm->ws1p[(cp * 3 + 0) * 2]), dm, acc);
                acc = fma2(*reinterpret_cast<const ull*>(&sm->ws1p[(cp * 3 + 1) * 2]), d0, acc);
                acc = fma2(*reinterpret_cast<const ull*>(&sm->ws1p[(cp * 3 + 2) * 2]), dp, acc);
                const float2 u = unpk(acc);
                sm->a_s[2 * cp + 0][b + p + 1] = fmaxf(u.x, 0.f);
                sm->a_s[2 * cp + 1][b + p + 1] = fmaxf(u.y, 0.f);
            }
        }
    }
    __syncthreads();

    // --- phase 2: conv2 (FFMA2 oc-pair packed) + relu + max, per node --------
    const int g  = tid >> 7;     // oc group: channels 4g..4g+3 (warp-uniform)
    const int pg = tid & 127;
    const int lane = tid & 31;
    const int wig  = (tid >> 5) & 3;

    #pragma unroll
    for (int k = 0; k < NPB; k++) {
        if (k > 0) __syncthreads();   // separate red[] reads from next node's writes

        float mx0 = -1e30f, mx1 = -1e30f, mx2 = -1e30f, mx3 = -1e30f;

        if (pg < 125) {
            const int p0 = (pg << 2) + (k << 9);
            const ull b01 = *reinterpret_cast<const ull*>(&sm->bs2[4 * g]);
            const ull b23 = *reinterpret_cast<const ull*>(&sm->bs2[4 * g + 2]);
            ull acc[4][2];
            #pragma unroll
            for (int r = 0; r < 4; r++) { acc[r][0] = b01; acc[r][1] = b23; }

            #pragma unroll
            for (int ic = 0; ic < HID; ic++) {
                const float4 av0 = *reinterpret_cast<const float4*>(&sm->a_s[ic][p0]);
                const float2 av1 = *reinterpret_cast<const float2*>(&sm->a_s[ic][p0 + 4]);
                ull d[6];
                d[0] = dup2(av0.x); d[1] = dup2(av0.y); d[2] = dup2(av0.z);
                d[3] = dup2(av0.w); d[4] = dup2(av1.x); d[5] = dup2(av1.y);

                const ulonglong2 w0  = *reinterpret_cast<const ulonglong2*>(&sm->ws2p[(ic * 3 + 0) * 16 + 4 * g]);
                const ulonglong2 w1v = *reinterpret_cast<const ulonglong2*>(&sm->ws2p[(ic * 3 + 1) * 16 + 4 * g]);
                const ulonglong2 w2v = *reinterpret_cast<const ulonglong2*>(&sm->ws2p[(ic * 3 + 2) * 16 + 4 * g]);

                #pragma unroll
                for (int r = 0; r < 4; r++) {
                    acc[r][0] = fma2(w0.x,  d[r],     acc[r][0]);
                    acc[r][1] = fma2(w0.y,  d[r],     acc[r][1]);
                    acc[r][0] = fma2(w1v.x, d[r + 1], acc[r][0]);
                    acc[r][1] = fma2(w1v.y, d[r + 1], acc[r][1]);
                    acc[r][0] = fma2(w2v.x, d[r + 2], acc[r][0]);
                    acc[r][1] = fma2(w2v.y, d[r + 2], acc[r][1]);
                }
            }
            #pragma unroll
            for (int r = 0; r < 4; r++) {
                const float2 u0 = unpk(acc[r][0]);
                const float2 u1 = unpk(acc[r][1]);
                mx0 = fmaxf(mx0, u0.x); mx1 = fmaxf(mx1, u0.y);
                mx2 = fmaxf(mx2, u1.x); mx3 = fmaxf(mx3, u1.y);
            }
        }
        #pragma unroll
        for (int off = 16; off; off >>= 1) {
            mx0 = fmaxf(mx0, __shfl_xor_sync(0xffffffffu, mx0, off));
            mx1 = fmaxf(mx1, __shfl_xor_sync(0xffffffffu, mx1, off));
            mx2 = fmaxf(mx2, __shfl_xor_sync(0xffffffffu, mx2, off));
            mx3 = fmaxf(mx3, __shfl_xor_sync(0xffffffffu, mx3, off));
        }
        if (lane == 0) {
            sm->red[wig][4 * g + 0] = mx0;
            sm->red[wig][4 * g + 1] = mx1;
            sm->red[wig][4 * g + 2] = mx2;
            sm->red[wig][4 * g + 3] = mx3;
        }
        __syncthreads();
        if (tid < HID) {
            float m = fmaxf(fmaxf(sm->red[0][tid], sm->red[1][tid]),
                            fmaxf(sm->red[2][tid], sm->red[3][tid]));
            g_h0[(n0 + k) * HID + tid] = fmaxf(m, 0.f);
        }
    }
}

// ---------------- degree count (g_deg zeroed in conv_max) --------------------
__global__ void deg_count_kernel(const int* __restrict__ dst)
{
    int i = blockIdx.x * blockDim.x + threadIdx.x;
    if (i < NEDGE) atomicAdd(&g_deg[dst[i]], 1);
}

// ---------------- gcn1: dinv + linear + self-loop init -----------------------
__global__ void lin1_kernel(const float* __restrict__ W, const float* __restrict__ b)
{
    __shared__ float Ws[HID * HID];
    __shared__ float bs[HID];
    const int tid = threadIdx.x;
    if (tid < HID * HID) Ws[tid] = W[tid];
    if (tid < HID)       bs[tid] = b[tid];
    __syncthreads();

    const int i = blockIdx.x * blockDim.x + tid;
    if (i >= NNODES) return;

    float h[HID];
    const float4* hp = reinterpret_cast<const float4*>(&g_h0[i * HID]);
    #pragma unroll
    for (int q = 0; q < 4; q++) {
        float4 v = hp[q];
        h[q * 4 + 0] = v.x; h[q * 4 + 1] = v.y; h[q * 4 + 2] = v.z; h[q * 4 + 3] = v.w;
    }
    float acc[HID];
    #pragma unroll
    for (int c = 0; c < HID; c++) acc[c] = 0.f;
    #pragma unroll
    for (int in = 0; in < HID; in++) {
        const float hv = h[in];
        #pragma unroll
        for (int c = 0; c < HID; c++) acc[c] = fmaf(hv, Ws[in * HID + c], acc[c]);
    }
    const float di = rsqrtf((float)(g_deg[i] + 1));
    g_dinv[i] = di;
    const float d2 = di * di;
    #pragma unroll
    for (int c = 0; c < HID; c++) {
        g_lin1[i * HID + c] = acc[c];
        g_acc1[i * HID + c] = fmaf(d2, acc[c], bs[c]);
    }
}

// ---------------- gcn1: edge scatter (1 thread/edge, 4x red.v4.f32) ----------
__global__ void scatter1_kernel(const int* __restrict__ src, const int* __restrict__ dst)
{
    int e = blockIdx.x * blockDim.x + threadIdx.x;
    if (e >= NEDGE) return;
    const int s = src[e];
    const int d = dst[e];
    const float w = g_dinv[s] * g_dinv[d];
    const float4* vp = reinterpret_cast<const float4*>(&g_lin1[s * HID]);
    float* out = &g_acc1[d * HID];
    #pragma unroll
    for (int q = 0; q < 4; q++) {
        const float4 v = vp[q];
        red_add_v4(out + 4 * q, w * v.x, w * v.y, w * v.z, w * v.w);
    }
}

// ---------------- gcn2: relu + linear(16->3) + self-loop init ----------------
__global__ void lin2_kernel(const float* __restrict__ W, const float* __restrict__ b)
{
    __shared__ float Ws[HID * OUTC];
    __shared__ float bs[OUTC];
    const int tid = threadIdx.x;
    if (tid < HID * OUTC) Ws[tid] = W[tid];
    if (tid < OUTC)       bs[tid] = b[tid];
    __syncthreads();

    const int i = blockIdx.x * blockDim.x + tid;
    if (i >= NNODES) return;

    float h[HID];
    const float4* hp = reinterpret_cast<const float4*>(&g_acc1[i * HID]);
    #pragma unroll
    for (int q = 0; q < 4; q++) {
        float4 v = hp[q];
        h[q * 4 + 0] = fmaxf(v.x, 0.f); h[q * 4 + 1] = fmaxf(v.y, 0.f);
        h[q * 4 + 2] = fmaxf(v.z, 0.f); h[q * 4 + 3] = fmaxf(v.w, 0.f);
    }
    float acc[OUTC] = {0.f, 0.f, 0.f};
    #pragma unroll
    for (int in = 0; in < HID; in++) {
        const float hv = h[in];
        #pragma unroll
        for (int c = 0; c < OUTC; c++) acc[c] = fmaf(hv, Ws[in * OUTC + c], acc[c]);
    }
    const float di = g_dinv[i];
    const float d2 = di * di;
    #pragma unroll
    for (int c = 0; c < OUTC; c++) {
        g_lin2[i * 4 + c] = acc[c];
        g_acc2[i * 4 + c] = fmaf(d2, acc[c], bs[c]);
    }
    g_lin2[i * 4 + 3] = 0.f;
    g_acc2[i * 4 + 3] = 0.f;
}

// ---------------- gcn2: edge scatter (1 thread/edge, 1x red.v4.f32) ----------
__global__ void scatter2_kernel(const int* __restrict__ src, const int* __restrict__ dst)
{
    int e = blockIdx.x * blockDim.x + threadIdx.x;
    if (e >= NEDGE) return;
    const int s = src[e];
    const int d = dst[e];
    const float w = g_dinv[s] * g_dinv[d];
    const float4 v = *reinterpret_cast<const float4*>(&g_lin2[s * 4]);
    red_add_v4(&g_acc2[d * 4], w * v.x, w * v.y, w * v.z, 0.f);
}

// ---------------- log_softmax (fast-math intrinsics) -------------------------
__global__ void logsoftmax_kernel(float* __restrict__ out)
{
    int i = blockIdx.x * blockDim.x + threadIdx.x;
    if (i >= NNODES) return;
    const float z0 = g_acc2[i * 4 + 0];
    const float z1 = g_acc2[i * 4 + 1];
    const float z2 = g_acc2[i * 4 + 2];
    const float m  = fmaxf(z0, fmaxf(z1, z2));
    const float s  = __expf(z0 - m) + __expf(z1 - m) + __expf(z2 - m);
    const float l  = m + __logf(s);
    out[i * 3 + 0] = z0 - l;
    out[i * 3 + 1] = z1 - l;
    out[i * 3 + 2] = z2 - l;
}

// ---------------- launcher ---------------------------------------------------
extern "C" void kernel_launch(void* const* d_in, const int* in_sizes, int n_in,
                              void* d_out, int out_size)
{
    const float* x       = (const float*)d_in[0];
    const float* conv1_w = (const float*)d_in[1];
    const float* conv1_b = (const float*)d_in[2];
    const float* conv2_w = (const float*)d_in[3];
    const float* conv2_b = (const float*)d_in[4];
    const float* gcn1_w  = (const float*)d_in[5];
    const float* gcn1_b  = (const float*)d_in[6];
    const float* gcn2_w  = (const float*)d_in[7];
    const float* gcn2_b  = (const float*)d_in[8];
    const int*   edges   = (const int*)d_in[9];
    const int*   src     = edges;
    const int*   dst     = edges + NEDGE;
    float*       out     = (float*)d_out;

    cudaFuncSetAttribute(conv_max_kernel,
                         cudaFuncAttributeMaxDynamicSharedMemorySize,
                         CONV_SMEM_BYTES);

    conv_max_kernel<<<NGRID, 512, CONV_SMEM_BYTES>>>(x, conv1_w, conv1_b, conv2_w, conv2_b);

    deg_count_kernel<<<(NEDGE + 255) / 256, 256>>>(dst);

    lin1_kernel    <<<(NNODES + 255) / 256, 256>>>(gcn1_w, gcn1_b);
    scatter1_kernel<<<(NEDGE + 255) / 256, 256>>>(src, dst);

    lin2_kernel    <<<(NNODES + 255) / 256, 256>>>(gcn2_w, gcn2_b);
    scatter2_kernel<<<(NEDGE + 255) / 256, 256>>>(src, dst);

    logsoftmax_kernel<<<(NNODES + 255) / 256, 256>>>(out);
}

// round 15
// speedup vs baseline: 1.8754x; 1.0292x over previous
#include <cuda_runtime.h>
#include <math.h>

#define NNODES 30000
#define FIN    500
#define HID    16
#define OUTC   3
#define NEDGE  960000

#define NPB    3                 // nodes per conv block
#define NGRID  (NNODES / NPB)    // 10000

typedef unsigned long long ull;

// ---------------- scratch (static device arrays; no allocation) -------------
__device__ float g_h0  [NNODES * HID];
__device__ float g_lin1[NNODES * HID];
__device__ float g_acc1[NNODES * HID];
__device__ float g_lin2[NNODES * 4];
__device__ float g_acc2[NNODES * 4];
__device__ int   g_deg [NNODES];
__device__ float g_dinv[NNODES];

// ---------------- f32x2 packed-FMA helpers (sm_103a FFMA2) ------------------
__device__ __forceinline__ ull fma2(ull a, ull b, ull c)
{
    ull d;
    asm("fma.rn.f32x2 %0, %1, %2, %3;" : "=l"(d) : "l"(a), "l"(b), "l"(c));
    return d;
}
__device__ __forceinline__ ull dup2(float x)
{
    ull d;
    asm("mov.b64 %0, {%1, %1};" : "=l"(d) : "f"(x));
    return d;
}
__device__ __forceinline__ float2 unpk(ull v)
{
    float2 r;
    asm("mov.b64 {%0, %1}, %2;" : "=f"(r.x), "=f"(r.y) : "l"(v));
    return r;
}

// ---------------- 128-bit global float4 reduction (sm_90+) -------------------
__device__ __forceinline__ void red_add_v4(float* p, float a, float b, float c, float d)
{
    asm volatile("red.global.add.v4.f32 [%0], {%1, %2, %3, %4};"
                 :: "l"(p), "f"(a), "f"(b), "f"(c), "f"(d) : "memory");
}

// ---------------- conv smem: THREE nodes per block ----------------------------
struct ConvSm {
    float xs [512 * NPB];
    float a_s[HID][512 * NPB];
    float ws2p[HID * 3 * 16];     // [ic][tap][oc] transposed conv2 weights
    float ws1p[8 * 3 * 2];        // conv1 weights packed over channel pairs
    float bs1[16];
    float bs2[16];
    float red[NPB][4][16];        // per-node reduction buffers (no WAR barriers)
};
#define CONV_SMEM_BYTES ((int)sizeof(ConvSm))

// ---------------- fused conv1 -> relu -> conv2 -> relu -> max (3 nodes/blk) ---
__global__ __launch_bounds__(512, 2)
void conv_max_kernel(const float* __restrict__ x,
                     const float* __restrict__ w1, const float* __restrict__ b1,
                     const float* __restrict__ w2, const float* __restrict__ b2)
{
    extern __shared__ __align__(16) char smem_raw[];
    ConvSm* sm = reinterpret_cast<ConvSm*>(smem_raw);

    const int tid = threadIdx.x;
    const int n0  = blockIdx.x * NPB;

    // --- phase 0: load x (all nodes), stage weights, zero borders ------------
    {
        if (tid < NPB) g_deg[n0 + tid] = 0;

        #pragma unroll
        for (int it = 0; it < NPB; it++) {
            const int idx = tid + (it << 9);
            const int k   = idx >> 9;
            const int i   = idx & 511;
            sm->xs[idx] = (i >= 1 && i <= 500) ? x[(n0 + k) * FIN + (i - 1)] : 0.f;
        }

        if (tid < 32 * NPB) {
            const int k  = tid / 32;
            const int r  = tid - k * 32;
            const int ch = r >> 1;
            const int col = ((r & 1) ? 501 : 0) + (k << 9);
            sm->a_s[ch][col] = 0.f;
        }

        for (int i = tid; i < HID * 3 * HID; i += 512) {
            int ic  = i / 48;
            int rem = i - ic * 48;
            int t   = rem >> 4;
            int oc  = rem & 15;
            sm->ws2p[i] = w2[oc * 48 + ic * 3 + t];
        }
        if (tid >= 128 && tid < 176) {
            int j = tid - 128;
            int c = j / 3, t = j - c * 3;
            sm->ws1p[((c >> 1) * 3 + t) * 2 + (c & 1)] = w1[j];
        } else if (tid >= 176 && tid < 192) sm->bs1[tid - 176] = b1[tid - 176];
        else if (tid >= 192 && tid < 208)   sm->bs2[tid - 192] = b2[tid - 192];
    }
    __syncthreads();

    // --- phase 1: conv1 (FFMA2 over channel pairs) + relu, all nodes ---------
    #pragma unroll
    for (int it = 0; it < NPB; it++) {
        const int idx = tid + (it << 9);
        const int k   = idx >> 9;
        const int p   = idx & 511;
        if (p < FIN) {
            const int b = k << 9;
            const ull dm = dup2(sm->xs[b + p]);
            const ull d0 = dup2(sm->xs[b + p + 1]);
            const ull dp = dup2(sm->xs[b + p + 2]);
            #pragma unroll
            for (int cp = 0; cp < 8; cp++) {
                ull acc = *reinterpret_cast<const ull*>(&sm->bs1[2 * cp]);
                acc = fma2(*reinterpret_cast<const ull*>(&sm->ws1p[(cp * 3 + 0) * 2]), dm, acc);
                acc = fma2(*reinterpret_cast<const ull*>(&sm->ws1p[(cp * 3 + 1) * 2]), d0, acc);
                acc = fma2(*reinterpret_cast<const ull*>(&sm->ws1p[(cp * 3 + 2) * 2]), dp, acc);
                const float2 u = unpk(acc);
                sm->a_s[2 * cp + 0][b + p + 1] = fmaxf(u.x, 0.f);
                sm->a_s[2 * cp + 1][b + p + 1] = fmaxf(u.y, 0.f);
            }
        }
    }
    __syncthreads();

    // --- phase 2: conv2 (FFMA2 oc-pair packed) + relu + max, per node --------
    const int g    = tid >> 7;
    const int pg   = tid & 127;
    const int lane = tid & 31;
    const int wig  = (tid >> 5) & 3;

    const ull b01 = *reinterpret_cast<const ull*>(&sm->bs2[4 * g]);
    const ull b23 = *reinterpret_cast<const ull*>(&sm->bs2[4 * g + 2]);

    #pragma unroll
    for (int k = 0; k < NPB; k++) {
        float mx0 = -1e30f, mx1 = -1e30f, mx2 = -1e30f, mx3 = -1e30f;

        if (pg < 125) {
            const int p0 = (pg << 2) + (k << 9);
            ull acc[4][2];
            #pragma unroll
            for (int r = 0; r < 4; r++) { acc[r][0] = b01; acc[r][1] = b23; }

            #pragma unroll
            for (int ic = 0; ic < HID; ic++) {
                const float4 av0 = *reinterpret_cast<const float4*>(&sm->a_s[ic][p0]);
                const float2 av1 = *reinterpret_cast<const float2*>(&sm->a_s[ic][p0 + 4]);
                ull d[6];
                d[0] = dup2(av0.x); d[1] = dup2(av0.y); d[2] = dup2(av0.z);
                d[3] = dup2(av0.w); d[4] = dup2(av1.x); d[5] = dup2(av1.y);

                const ulonglong2 w0  = *reinterpret_cast<const ulonglong2*>(&sm->ws2p[(ic * 3 + 0) * 16 + 4 * g]);
                const ulonglong2 w1v = *reinterpret_cast<const ulonglong2*>(&sm->ws2p[(ic * 3 + 1) * 16 + 4 * g]);
                const ulonglong2 w2v = *reinterpret_cast<const ulonglong2*>(&sm->ws2p[(ic * 3 + 2) * 16 + 4 * g]);

                #pragma unroll
                for (int r = 0; r < 4; r++) {
                    acc[r][0] = fma2(w0.x,  d[r],     acc[r][0]);
                    acc[r][1] = fma2(w0.y,  d[r],     acc[r][1]);
                    acc[r][0] = fma2(w1v.x, d[r + 1], acc[r][0]);
                    acc[r][1] = fma2(w1v.y, d[r + 1], acc[r][1]);
                    acc[r][0] = fma2(w2v.x, d[r + 2], acc[r][0]);
                    acc[r][1] = fma2(w2v.y, d[r + 2], acc[r][1]);
                }
            }
            #pragma unroll
            for (int r = 0; r < 4; r++) {
                const float2 u0 = unpk(acc[r][0]);
                const float2 u1 = unpk(acc[r][1]);
                mx0 = fmaxf(mx0, u0.x); mx1 = fmaxf(mx1, u0.y);
                mx2 = fmaxf(mx2, u1.x); mx3 = fmaxf(mx3, u1.y);
            }
        }
        #pragma unroll
        for (int off = 16; off; off >>= 1) {
            mx0 = fmaxf(mx0, __shfl_xor_sync(0xffffffffu, mx0, off));
            mx1 = fmaxf(mx1, __shfl_xor_sync(0xffffffffu, mx1, off));
            mx2 = fmaxf(mx2, __shfl_xor_sync(0xffffffffu, mx2, off));
            mx3 = fmaxf(mx3, __shfl_xor_sync(0xffffffffu, mx3, off));
        }
        if (lane == 0) {
            sm->red[k][wig][4 * g + 0] = mx0;
            sm->red[k][wig][4 * g + 1] = mx1;
            sm->red[k][wig][4 * g + 2] = mx2;
            sm->red[k][wig][4 * g + 3] = mx3;
        }
    }
    __syncthreads();

    // finalize all NPB nodes with one pass
    if (tid < HID * NPB) {
        const int k = tid >> 4;
        const int c = tid & 15;
        float m = fmaxf(fmaxf(sm->red[k][0][c], sm->red[k][1][c]),
                        fmaxf(sm->red[k][2][c], sm->red[k][3][c]));
        g_h0[(n0 + k) * HID + c] = fmaxf(m, 0.f);
    }
}

// ---------------- degree count (4 edges/thread, int4 loads) ------------------
__global__ void deg_count_kernel(const int* __restrict__ dst)
{
    int i = blockIdx.x * blockDim.x + threadIdx.x;   // quad index
    if (i * 4 >= NEDGE) return;
    const int4 e4 = *reinterpret_cast<const int4*>(dst + i * 4);   // NEDGE % 4 == 0
    atomicAdd(&g_deg[e4.x], 1);
    atomicAdd(&g_deg[e4.y], 1);
    atomicAdd(&g_deg[e4.z], 1);
    atomicAdd(&g_deg[e4.w], 1);
}

// ---------------- gcn1: dinv + linear + self-loop init -----------------------
__global__ void lin1_kernel(const float* __restrict__ W, const float* __restrict__ b)
{
    __shared__ float Ws[HID * HID];
    __shared__ float bs[HID];
    const int tid = threadIdx.x;
    if (tid < HID * HID) Ws[tid] = W[tid];
    if (tid < HID)       bs[tid] = b[tid];
    __syncthreads();

    const int i = blockIdx.x * blockDim.x + tid;
    if (i >= NNODES) return;

    float h[HID];
    const float4* hp = reinterpret_cast<const float4*>(&g_h0[i * HID]);
    #pragma unroll
    for (int q = 0; q < 4; q++) {
        float4 v = hp[q];
        h[q * 4 + 0] = v.x; h[q * 4 + 1] = v.y; h[q * 4 + 2] = v.z; h[q * 4 + 3] = v.w;
    }
    float acc[HID];
    #pragma unroll
    for (int c = 0; c < HID; c++) acc[c] = 0.f;
    #pragma unroll
    for (int in = 0; in < HID; in++) {
        const float hv = h[in];
        #pragma unroll
        for (int c = 0; c < HID; c++) acc[c] = fmaf(hv, Ws[in * HID + c], acc[c]);
    }
    const float di = rsqrtf((float)(g_deg[i] + 1));
    g_dinv[i] = di;
    const float d2 = di * di;
    #pragma unroll
    for (int c = 0; c < HID; c++) {
        g_lin1[i * HID + c] = acc[c];
        g_acc1[i * HID + c] = fmaf(d2, acc[c], bs[c]);
    }
}

// ---------------- gcn1: edge scatter (1 thread/edge, 4x red.v4.f32) ----------
__global__ void scatter1_kernel(const int* __restrict__ src, const int* __restrict__ dst)
{
    int e = blockIdx.x * blockDim.x + threadIdx.x;
    if (e >= NEDGE) return;
    const int s = src[e];
    const int d = dst[e];
    const float w = g_dinv[s] * g_dinv[d];
    const float4* vp = reinterpret_cast<const float4*>(&g_lin1[s * HID]);
    float* out = &g_acc1[d * HID];
    #pragma unroll
    for (int q = 0; q < 4; q++) {
        const float4 v = vp[q];
        red_add_v4(out + 4 * q, w * v.x, w * v.y, w * v.z, w * v.w);
    }
}

// ---------------- gcn2: relu + linear(16->3) + self-loop init ----------------
__global__ void lin2_kernel(const float* __restrict__ W, const float* __restrict__ b)
{
    __shared__ float Ws[HID * OUTC];
    __shared__ float bs[OUTC];
    const int tid = threadIdx.x;
    if (tid < HID * OUTC) Ws[tid] = W[tid];
    if (tid < OUTC)       bs[tid] = b[tid];
    __syncthreads();

    const int i = blockIdx.x * blockDim.x + tid;
    if (i >= NNODES) return;

    float h[HID];
    const float4* hp = reinterpret_cast<const float4*>(&g_acc1[i * HID]);
    #pragma unroll
    for (int q = 0; q < 4; q++) {
        float4 v = hp[q];
        h[q * 4 + 0] = fmaxf(v.x, 0.f); h[q * 4 + 1] = fmaxf(v.y, 0.f);
        h[q * 4 + 2] = fmaxf(v.z, 0.f); h[q * 4 + 3] = fmaxf(v.w, 0.f);
    }
    float acc[OUTC] = {0.f, 0.f, 0.f};
    #pragma unroll
    for (int in = 0; in < HID; in++) {
        const float hv = h[in];
        #pragma unroll
        for (int c = 0; c < OUTC; c++) acc[c] = fmaf(hv, Ws[in * OUTC + c], acc[c]);
    }
    const float di = g_dinv[i];
    const float d2 = di * di;
    #pragma unroll
    for (int c = 0; c < OUTC; c++) {
        g_lin2[i * 4 + c] = acc[c];
        g_acc2[i * 4 + c] = fmaf(d2, acc[c], bs[c]);
    }
    g_lin2[i * 4 + 3] = 0.f;
    g_acc2[i * 4 + 3] = 0.f;
}

// ---------------- gcn2: edge scatter (1 thread/edge, 1x red.v4.f32) ----------
__global__ void scatter2_kernel(const int* __restrict__ src, const int* __restrict__ dst)
{
    int e = blockIdx.x * blockDim.x + threadIdx.x;
    if (e >= NEDGE) return;
    const int s = src[e];
    const int d = dst[e];
    const float w = g_dinv[s] * g_dinv[d];
    const float4 v = *reinterpret_cast<const float4*>(&g_lin2[s * 4]);
    red_add_v4(&g_acc2[d * 4], w * v.x, w * v.y, w * v.z, 0.f);
}

// ---------------- log_softmax (fast-math intrinsics) -------------------------
__global__ void logsoftmax_kernel(float* __restrict__ out)
{
    int i = blockIdx.x * blockDim.x + threadIdx.x;
    if (i >= NNODES) return;
    const float z0 = g_acc2[i * 4 + 0];
    const float z1 = g_acc2[i * 4 + 1];
    const float z2 = g_acc2[i * 4 + 2];
    const float m  = fmaxf(z0, fmaxf(z1, z2));
    const float s  = __expf(z0 - m) + __expf(z1 - m) + __expf(z2 - m);
    const float l  = m + __logf(s);
    out[i * 3 + 0] = z0 - l;
    out[i * 3 + 1] = z1 - l;
    out[i * 3 + 2] = z2 - l;
}

// ---------------- launcher ---------------------------------------------------
extern "C" void kernel_launch(void* const* d_in, const int* in_sizes, int n_in,
                              void* d_out, int out_size)
{
    const float* x       = (const float*)d_in[0];
    const float* conv1_w = (const float*)d_in[1];
    const float* conv1_b = (const float*)d_in[2];
    const float* conv2_w = (const float*)d_in[3];
    const float* conv2_b = (const float*)d_in[4];
    const float* gcn1_w  = (const float*)d_in[5];
    const float* gcn1_b  = (const float*)d_in[6];
    const float* gcn2_w  = (const float*)d_in[7];
    const float* gcn2_b  = (const float*)d_in[8];
    const int*   edges   = (const int*)d_in[9];
    const int*   src     = edges;
    const int*   dst     = edges + NEDGE;
    float*       out     = (float*)d_out;

    cudaFuncSetAttribute(conv_max_kernel,
                         cudaFuncAttributeMaxDynamicSharedMemorySize,
                         CONV_SMEM_BYTES);

    conv_max_kernel<<<NGRID, 512, CONV_SMEM_BYTES>>>(x, conv1_w, conv1_b, conv2_w, conv2_b);

    deg_count_kernel<<<(NEDGE / 4 + 255) / 256, 256>>>(dst);

    lin1_kernel    <<<(NNODES + 255) / 256, 256>>>(gcn1_w, gcn1_b);
    scatter1_kernel<<<(NEDGE + 255) / 256, 256>>>(src, dst);

    lin2_kernel    <<<(NNODES + 255) / 256, 256>>>(gcn2_w, gcn2_b);
    scatter2_kernel<<<(NEDGE + 255) / 256, 256>>>(src, dst);

    logsoftmax_kernel<<<(NNODES + 255) / 256, 256>>>(out);
}